// round 15
// baseline (speedup 1.0000x reference)
#include <cuda_runtime.h>

// x: [8,32,512] fp32, w_q/w_k/w_v: [1,128] fp32, out: [8,32,128] fp32
#define BV      256
#define FDIM    512
#define DMODEL  128
#define MNODES  16
#define TPB     512
#define NW      (TPB / 32)      // 16 warps

// cos(pi*m/32), m = 0..63 (compile-time; replaces cospif on the critical path)
__device__ const float g_cos64[64] = {
     1.000000000f,  0.995184727f,  0.980785280f,  0.956940336f,
     0.923879533f,  0.881921264f,  0.831469612f,  0.773010453f,
     0.707106781f,  0.634393284f,  0.555570233f,  0.471396737f,
     0.382683432f,  0.290284677f,  0.195090322f,  0.098017140f,
     0.000000000f, -0.098017140f, -0.195090322f, -0.290284677f,
    -0.382683432f, -0.471396737f, -0.555570233f, -0.634393284f,
    -0.707106781f, -0.773010453f, -0.831469612f, -0.881921264f,
    -0.923879533f, -0.956940336f, -0.980785280f, -0.995184727f,
    -1.000000000f, -0.995184727f, -0.980785280f, -0.956940336f,
    -0.923879533f, -0.881921264f, -0.831469612f, -0.773010453f,
    -0.707106781f, -0.634393284f, -0.555570233f, -0.471396737f,
    -0.382683432f, -0.290284677f, -0.195090322f, -0.098017140f,
     0.000000000f,  0.098017140f,  0.195090322f,  0.290284677f,
     0.382683432f,  0.471396737f,  0.555570233f,  0.634393284f,
     0.707106781f,  0.773010453f,  0.831469612f,  0.881921264f,
     0.923879533f,  0.956940336f,  0.980785280f,  0.995184727f
};

__device__ __forceinline__ float ex2f(float a) {
    float r; asm("ex2.approx.ftz.f32 %0, %1;" : "=f"(r) : "f"(a)); return r;
}

__global__ __launch_bounds__(TPB)
void attn_cheb_kernel(const float* __restrict__ x,
                      const float* __restrict__ wq,
                      const float* __restrict__ wk,
                      const float* __restrict__ wv,
                      float* __restrict__ out)
{
    __shared__ __align__(16) float sx[FDIM];
    __shared__ __align__(16) float sWv[DMODEL];   // hoisted w_v row
    __shared__ float sTbl[64];          // cos(pi*m/32)
    __shared__ float sS[MNODES];        // s(t_j) at Chebyshev nodes
    __shared__ float sC[MNODES];        // Chebyshev coefficients
    __shared__ float sRp[NW], sRmx[NW], sRmn[NW], sRs[NW];

    const int tid  = threadIdx.x;
    const int lane = tid & 31;
    const int warp = tid >> 5;
    const int bv   = blockIdx.x;
    const float* __restrict__ xr = x + bv * FDIM;

    // ---- Phase 1: stage x row, cos table, wv row; row min/max; K partials ----
    float v = xr[tid];
    sx[tid] = v;
    if (tid < 64) sTbl[tid] = g_cos64[tid];                   // coalesced LDG
    if (warp == 2) ((float4*)sWv)[lane] = ((const float4*)wv)[lane];  // wv off tail
    float lmax = v, lmin = v;
    float p = (tid < DMODEL) ? wq[tid] * wk[tid] : 0.0f;
    #pragma unroll
    for (int s = 16; s > 0; s >>= 1) {
        p   += __shfl_xor_sync(~0u, p, s);
        lmax = fmaxf(lmax, __shfl_xor_sync(~0u, lmax, s));
        lmin = fminf(lmin, __shfl_xor_sync(~0u, lmin, s));
    }
    if (lane == 0) { sRp[warp] = p; sRmx[warp] = lmax; sRmn[warp] = lmin; }
    __syncthreads();                                                   // B1

    // Every thread redundantly finalizes the block scalars (bitwise identical).
    float P = 0.0f, Mx = sRmx[0], Mn = sRmn[0];
    #pragma unroll
    for (int w = 0; w < NW; w++) {
        P += sRp[w];
        Mx = fmaxf(Mx, sRmx[w]);
        Mn = fminf(Mn, sRmn[w]);
    }
    const float K   = P * (1.4426950408889634f * 0.08838834764831845f); // log2e/sqrt(128)
    const float ta  = K * Mn, tb = K * Mx;
    const float cen = 0.5f * (ta + tb);
    float h = 0.5f * fabsf(tb - ta);
    if (h < 1e-30f) h = 1e-30f;
    const float hinv = 1.0f / h;

    // Hoist Clenshaw argument off the post-B3 path.
    float u = (K * sx[tid] - cen) * hinv;
    u = fminf(fmaxf(u, -1.0f), 1.0f);
    const float tu = u + u;

    // ---- Phase 2: sample s(t) at 16 nodes; warp w -> node w ----
    {
        const float tj = fmaf(h, sTbl[2 * warp + 1], cen);  // cen + h*cos(pi(2w+1)/32)
        const float Mj = (tj >= 0.0f) ? tj * Mx : tj * Mn;
        float da = 0.f, db = 0.f, na = 0.f, nb = 0.f;
        const float4* __restrict__ sx4 = (const float4*)sx;
        #pragma unroll
        for (int i = 0; i < FDIM / 128; i++) {      // 4 iters x float4 = 16 g/lane
            float4 g = sx4[lane + 32 * i];
            float e0 = ex2f(fmaf(tj, g.x, -Mj));
            float e1 = ex2f(fmaf(tj, g.y, -Mj));
            float e2 = ex2f(fmaf(tj, g.z, -Mj));
            float e3 = ex2f(fmaf(tj, g.w, -Mj));
            da += e0; db += e1; da += e2; db += e3;
            na = fmaf(e0, g.x, na); nb = fmaf(e1, g.y, nb);
            na = fmaf(e2, g.z, na); nb = fmaf(e3, g.w, nb);
        }
        float den = da + db, num = na + nb;
        #pragma unroll
        for (int s = 16; s > 0; s >>= 1) {
            den += __shfl_xor_sync(~0u, den, s);
            num += __shfl_xor_sync(~0u, num, s);
        }
        if (lane == 0) sS[warp] = num / den;
    }
    __syncthreads();                                                   // B2

    // ---- Phase 3: parallel DCT; warp w -> coefficient k = w ----
    {
        float a = 0.0f;
        if (lane < MNODES) {
            int m = (warp * (2 * lane + 1)) & 63;   // angle pi*m/32 mod 2pi
            a = sS[lane] * sTbl[m];
        }
        #pragma unroll
        for (int s = 8; s > 0; s >>= 1)
            a += __shfl_xor_sync(~0u, a, s);
        if (lane == 0)
            sC[warp] = a * (2.0f / MNODES) * (warp == 0 ? 0.5f : 1.0f);
    }
    __syncthreads();                                                   // B3

    // ---- Phase 4: Clenshaw eval s(t_f), 1 f per thread ----
    float sf;
    {
        float b1 = 0.0f, b2 = 0.0f;
        #pragma unroll
        for (int k = MNODES - 1; k >= 1; k--) {
            float b = fmaf(tu, b1, sC[k] - b2);
            b2 = b1; b1 = b;
        }
        sf = fmaf(u, b1, sC[0] - b2);
    }

    // ---- Phase 5: mean over f; warp 0 writes the row (wv from smem) ----
    #pragma unroll
    for (int s = 16; s > 0; s >>= 1)
        sf += __shfl_xor_sync(~0u, sf, s);
    if (lane == 0) sRs[warp] = sf;
    __syncthreads();                                                   // B4
    if (warp == 0) {
        float m = (lane < NW) ? sRs[lane] : 0.0f;
        #pragma unroll
        for (int s = 8; s > 0; s >>= 1)
            m += __shfl_xor_sync(~0u, m, s);
        m = __shfl_sync(~0u, m, 0) * (1.0f / 512.0f);
        float4 w = ((const float4*)sWv)[lane];      // LDS, not LDG
        float4 o = make_float4(m * w.x, m * w.y, m * w.z, m * w.w);
        ((float4*)out)[bv * (DMODEL / 4) + lane] = o;
    }
}

extern "C" void kernel_launch(void* const* d_in, const int* in_sizes, int n_in,
                              void* d_out, int out_size)
{
    const float* x  = (const float*)d_in[0];
    const float* wq = (const float*)d_in[1];
    const float* wk = (const float*)d_in[2];
    const float* wv = (const float*)d_in[3];
    float* out = (float*)d_out;

    attn_cheb_kernel<<<BV, TPB>>>(x, wq, wk, wv, out);
}

// round 17
// speedup vs baseline: 1.3286x; 1.3286x over previous
#include <cuda_runtime.h>

// x: [8,32,512] fp32, w_q/w_k/w_v: [1,128] fp32, out: [8,32,128] fp32
#define BV      256
#define FDIM    512
#define DMODEL  128
#define MNODES  16
#define TPB     512
#define NW      (TPB / 32)      // 16 warps

// cos(pi*m/32), m = 0..63
__device__ const float g_cos64[64] = {
     1.000000000f,  0.995184727f,  0.980785280f,  0.956940336f,
     0.923879533f,  0.881921264f,  0.831469612f,  0.773010453f,
     0.707106781f,  0.634393284f,  0.555570233f,  0.471396737f,
     0.382683432f,  0.290284677f,  0.195090322f,  0.098017140f,
     0.000000000f, -0.098017140f, -0.195090322f, -0.290284677f,
    -0.382683432f, -0.471396737f, -0.555570233f, -0.634393284f,
    -0.707106781f, -0.773010453f, -0.831469612f, -0.881921264f,
    -0.923879533f, -0.956940336f, -0.980785280f, -0.995184727f,
    -1.000000000f, -0.995184727f, -0.980785280f, -0.956940336f,
    -0.923879533f, -0.881921264f, -0.831469612f, -0.773010453f,
    -0.707106781f, -0.634393284f, -0.555570233f, -0.471396737f,
    -0.382683432f, -0.290284677f, -0.195090322f, -0.098017140f,
     0.000000000f,  0.098017140f,  0.195090322f,  0.290284677f,
     0.382683432f,  0.471396737f,  0.555570233f,  0.634393284f,
     0.707106781f,  0.773010453f,  0.831469612f,  0.881921264f,
     0.923879533f,  0.956940336f,  0.980785280f,  0.995184727f
};

__device__ __forceinline__ float ex2f(float a) {
    float r; asm("ex2.approx.ftz.f32 %0, %1;" : "=f"(r) : "f"(a)); return r;
}

__global__ __launch_bounds__(TPB)
void attn_cheb_kernel(const float* __restrict__ x,
                      const float* __restrict__ wq,
                      const float* __restrict__ wk,
                      const float* __restrict__ wv,
                      float* __restrict__ out)
{
    __shared__ __align__(16) float sx[FDIM];
    __shared__ __align__(16) float sWv[DMODEL];   // hoisted w_v row
    __shared__ float sTbl[64];          // cos(pi*m/32)
    __shared__ float sS[MNODES];        // s(t_j) at Chebyshev nodes
    __shared__ float sC[MNODES];        // Chebyshev coefficients
    __shared__ float sRp[NW], sRmx[NW], sRmn[NW], sRs[NW];

    const int tid  = threadIdx.x;
    const int lane = tid & 31;
    const int warp = tid >> 5;
    const int bv   = blockIdx.x;
    const float* __restrict__ xr = x + bv * FDIM;

    // ---- Phase 1: stage x row, cos table, wv row; row min/max; K partials ----
    float v = xr[tid];
    sx[tid] = v;
    if (tid < 64) sTbl[tid] = g_cos64[tid];                   // coalesced LDG
    if (warp == 2) ((float4*)sWv)[lane] = ((const float4*)wv)[lane];  // wv off tail
    float lmax = v, lmin = v;
    float p = (tid < DMODEL) ? wq[tid] * wk[tid] : 0.0f;
    #pragma unroll
    for (int s = 16; s > 0; s >>= 1) {
        p   += __shfl_xor_sync(~0u, p, s);
        lmax = fmaxf(lmax, __shfl_xor_sync(~0u, lmax, s));
        lmin = fminf(lmin, __shfl_xor_sync(~0u, lmin, s));
    }
    if (lane == 0) { sRp[warp] = p; sRmx[warp] = lmax; sRmn[warp] = lmin; }
    __syncthreads();                                                   // B1

    // Every thread redundantly finalizes the block scalars (bitwise identical).
    float P = 0.0f, Mx = sRmx[0], Mn = sRmn[0];
    #pragma unroll
    for (int w = 0; w < NW; w++) {
        P += sRp[w];
        Mx = fmaxf(Mx, sRmx[w]);
        Mn = fminf(Mn, sRmn[w]);
    }
    const float K   = P * (1.4426950408889634f * 0.08838834764831845f); // log2e/sqrt(128)
    const float ta  = K * Mn, tb = K * Mx;
    const float cen = 0.5f * (ta + tb);
    float h = 0.5f * fabsf(tb - ta);
    if (h < 1e-30f) h = 1e-30f;
    const float hinv = 1.0f / h;

    // Hoist Clenshaw argument off the post-B3 path.
    float u = (K * sx[tid] - cen) * hinv;
    u = fminf(fmaxf(u, -1.0f), 1.0f);
    const float tu = u + u;

    // ---- Phase 2: sample s(t) at 16 nodes; warp w -> node w ----
    {
        const float tj = fmaf(h, sTbl[2 * warp + 1], cen);  // cen + h*cos(pi(2w+1)/32)
        const float Mj = (tj >= 0.0f) ? tj * Mx : tj * Mn;
        float da = 0.f, db = 0.f, na = 0.f, nb = 0.f;
        const float4* __restrict__ sx4 = (const float4*)sx;
        #pragma unroll
        for (int i = 0; i < FDIM / 128; i++) {      // 4 iters x float4 = 16 g/lane
            float4 g = sx4[lane + 32 * i];
            float e0 = ex2f(fmaf(tj, g.x, -Mj));
            float e1 = ex2f(fmaf(tj, g.y, -Mj));
            float e2 = ex2f(fmaf(tj, g.z, -Mj));
            float e3 = ex2f(fmaf(tj, g.w, -Mj));
            da += e0; db += e1; da += e2; db += e3;
            na = fmaf(e0, g.x, na); nb = fmaf(e1, g.y, nb);
            na = fmaf(e2, g.z, na); nb = fmaf(e3, g.w, nb);
        }
        float den = da + db, num = na + nb;
        #pragma unroll
        for (int s = 16; s > 0; s >>= 1) {          // two chains interleave/pipeline
            den += __shfl_xor_sync(~0u, den, s);
            num += __shfl_xor_sync(~0u, num, s);
        }
        if (lane == 0) sS[warp] = num / den;
    }
    __syncthreads();                                                   // B2

    // ---- Phase 3: parallel DCT; warp w -> coefficient k = w ----
    {
        float a = 0.0f;
        if (lane < MNODES) {
            int m = (warp * (2 * lane + 1)) & 63;   // angle pi*m/32 mod 2pi
            a = sS[lane] * sTbl[m];
        }
        #pragma unroll
        for (int s = 8; s > 0; s >>= 1)             // width-16: lanes 16+ are zero
            a += __shfl_xor_sync(~0u, a, s);
        if (lane == 0)
            sC[warp] = a * (2.0f / MNODES) * (warp == 0 ? 0.5f : 1.0f);
    }
    __syncthreads();                                                   // B3

    // ---- Phase 4: Clenshaw eval s(t_f), 1 f per thread ----
    float sf;
    {
        float b1 = 0.0f, b2 = 0.0f;
        #pragma unroll
        for (int k = MNODES - 1; k >= 1; k--) {
            float b = fmaf(tu, b1, sC[k] - b2);
            b2 = b1; b1 = b;
        }
        sf = fmaf(u, b1, sC[0] - b2);
    }

    // ---- Phase 5: mean over f; warp 0 writes the row (wv from smem) ----
    #pragma unroll
    for (int s = 16; s > 0; s >>= 1)
        sf += __shfl_xor_sync(~0u, sf, s);
    if (lane == 0) sRs[warp] = sf;
    __syncthreads();                                                   // B4
    if (warp == 0) {
        float m = (lane < NW) ? sRs[lane] : 0.0f;
        #pragma unroll
        for (int s = 8; s > 0; s >>= 1)
            m += __shfl_xor_sync(~0u, m, s);
        m = __shfl_sync(~0u, m, 0) * (1.0f / 512.0f);
        float4 w = ((const float4*)sWv)[lane];      // LDS, not LDG
        float4 o = make_float4(m * w.x, m * w.y, m * w.z, m * w.w);
        ((float4*)out)[bv * (DMODEL / 4) + lane] = o;
    }
}

extern "C" void kernel_launch(void* const* d_in, const int* in_sizes, int n_in,
                              void* d_out, int out_size)
{
    const float* x  = (const float*)d_in[0];
    const float* wq = (const float*)d_in[1];
    const float* wk = (const float*)d_in[2];
    const float* wv = (const float*)d_in[3];
    float* out = (float*)d_out;

    attn_cheb_kernel<<<BV, TPB>>>(x, wq, wk, wv, out);
}